// round 1
// baseline (speedup 1.0000x reference)
#include <cuda_runtime.h>
#include <math.h>

// Problem constants (fixed shapes per reference setup_inputs)
#define BATCH  4096
#define DIN    128
#define DOUT   128
#define NB     9            // basis functions
#define KSPLIT 4            // split-K factor over Din
#define ISPLIT (DIN / KSPLIT)  // 32 i's per split
#define BM     128          // batch rows per block

// Scratch (allocation-free: __device__ globals)
__device__ float g_Wt[DIN * NB * DOUT];            // [(i*9+k)][o], 576 KB
__device__ float g_beta[DOUT];
__device__ float g_part[KSPLIT * BATCH * DOUT];    // 8 MB partials

// ---------------------------------------------------------------------------
// Prep: Wt[(i,k),o] = W[i,o,k] * C[i,o]
// ---------------------------------------------------------------------------
__global__ void kan_prep(const float* __restrict__ W, const float* __restrict__ C) {
    int idx = blockIdx.x * blockDim.x + threadIdx.x;   // over Din*Dout*NB
    if (idx < DIN * DOUT * NB) {
        int k = idx % NB;
        int o = (idx / NB) % DOUT;
        int i = idx / (NB * DOUT);
        g_Wt[(i * NB + k) * DOUT + o] = W[idx] * C[i * DOUT + o];
    }
}

// beta[o] = sum_i bias[i,o] * C[i,o]
__global__ void kan_beta(const float* __restrict__ bias, const float* __restrict__ C) {
    int o = threadIdx.x;
    float s = 0.0f;
    #pragma unroll 8
    for (int i = 0; i < DIN; ++i)
        s += bias[i * DOUT + o] * C[i * DOUT + o];
    g_beta[o] = s;
}

// ---------------------------------------------------------------------------
// Main: fused basis + GEMM, 128x128 block tile, 8x8 per-thread micro-tile,
// split-K over Din. Grid (BATCH/BM, KSPLIT), 256 threads.
// ---------------------------------------------------------------------------
__global__ __launch_bounds__(256)
void kan_main(const float* __restrict__ x) {
    __shared__ float As[NB][BM];     // feats for current i, k-major rows
    __shared__ float Bs[NB][DOUT];   // Wt rows (i*9+k) for current i

    const int bm0   = blockIdx.x * BM;
    const int split = blockIdx.y;
    const int i0    = split * ISPLIT;
    const int t     = threadIdx.x;           // 0..255
    const int tx    = t & 15;                // column group
    const int ty    = t >> 4;                // row group
    const int row0  = ty * 8;
    const int col0  = tx * 8;

    float acc[8][8];
    #pragma unroll
    for (int r = 0; r < 8; ++r)
        #pragma unroll
        for (int c = 0; c < 8; ++c) acc[r][c] = 0.0f;

    for (int ii = 0; ii < ISPLIT; ++ii) {
        const int i = i0 + ii;

        __syncthreads();  // previous compute done before smem overwrite

        // --- A tile: basis expansion of x[bm0..bm0+127, i], one row per thread
        if (t < BM) {
            float xv = x[(bm0 + t) * DIN + i];
            float ax = fabsf(xv);
            As[0][t] = xv;
            As[1][t] = xv * xv;
            As[2][t] = xv * xv * xv;
            As[3][t] = expf(xv);
            As[4][t] = log1pf(ax);
            As[5][t] = sqrtf(ax);
            As[6][t] = tanhf(xv);
            As[7][t] = sinf(xv);
            As[8][t] = ax;
        }

        // --- B tile: 9x128 floats of Wt (288 float4 by 256 threads)
        {
            const float4* src = reinterpret_cast<const float4*>(&g_Wt[i * NB * DOUT]);
            float4*       dst = reinterpret_cast<float4*>(&Bs[0][0]);
            dst[t] = src[t];
            if (t < (NB * DOUT / 4 - 256))     // 32 extra
                dst[256 + t] = src[256 + t];
        }

        __syncthreads();

        // --- 8x8 register-tiled FMA over the 9 basis rows
        #pragma unroll
        for (int k = 0; k < NB; ++k) {
            float4 a0 = *reinterpret_cast<const float4*>(&As[k][row0]);
            float4 a1 = *reinterpret_cast<const float4*>(&As[k][row0 + 4]);
            float4 b0 = *reinterpret_cast<const float4*>(&Bs[k][col0]);
            float4 b1 = *reinterpret_cast<const float4*>(&Bs[k][col0 + 4]);
            float a[8] = {a0.x, a0.y, a0.z, a0.w, a1.x, a1.y, a1.z, a1.w};
            float b[8] = {b0.x, b0.y, b0.z, b0.w, b1.x, b1.y, b1.z, b1.w};
            #pragma unroll
            for (int r = 0; r < 8; ++r)
                #pragma unroll
                for (int c = 0; c < 8; ++c)
                    acc[r][c] += a[r] * b[c];
        }
    }

    // --- write partials (coalesced float4)
    float* outp = &g_part[(size_t)(split * BATCH + bm0) * DOUT];
    #pragma unroll
    for (int r = 0; r < 8; ++r) {
        const int b = row0 + r;
        #pragma unroll
        for (int c = 0; c < 8; c += 4) {
            float4 v = make_float4(acc[r][c], acc[r][c + 1], acc[r][c + 2], acc[r][c + 3]);
            *reinterpret_cast<float4*>(&outp[b * DOUT + col0 + c]) = v;
        }
    }
}

// ---------------------------------------------------------------------------
// Reduce partials + beta -> out
// ---------------------------------------------------------------------------
__global__ void kan_reduce(float* __restrict__ out) {
    int idx = blockIdx.x * blockDim.x + threadIdx.x;   // over BATCH*DOUT
    int o = idx & (DOUT - 1);
    float s = g_beta[o];
    #pragma unroll
    for (int sp = 0; sp < KSPLIT; ++sp)
        s += g_part[(size_t)sp * BATCH * DOUT + idx];
    out[idx] = s;
}

// ---------------------------------------------------------------------------
extern "C" void kernel_launch(void* const* d_in, const int* in_sizes, int n_in,
                              void* d_out, int out_size) {
    const float* x    = (const float*)d_in[0];   // [4096,128]
    const float* W    = (const float*)d_in[1];   // [128,128,9]
    const float* bias = (const float*)d_in[2];   // [128,128]
    const float* C    = (const float*)d_in[3];   // [128,128]
    float* out        = (float*)d_out;           // [4096,128]

    (void)in_sizes; (void)n_in; (void)out_size;

    kan_prep<<<(DIN * DOUT * NB + 255) / 256, 256>>>(W, C);
    kan_beta<<<1, DOUT>>>(bias, C);
    kan_main<<<dim3(BATCH / BM, KSPLIT), 256>>>(x);
    kan_reduce<<<(BATCH * DOUT) / 256, 256>>>(out);
}

// round 3
// speedup vs baseline: 1.1565x; 1.1565x over previous
#include <cuda_runtime.h>
#include <cstdint>
#include <math.h>

// ---------------------------------------------------------------------------
// Problem constants
// ---------------------------------------------------------------------------
#define BATCH   4096
#define DIN     128
#define DOUT    128
#define NB      9
#define KSPLIT  4
#define ISPLIT  (DIN / KSPLIT)     // 32 input dims per split block
#define BM      128                // batch rows per block
#define NITER   (ISPLIT / 2)       // 16 iterations, 2 input dims each
#define NTILE   (BATCH / BM)       // 32 batch tiles

// ---------------------------------------------------------------------------
// Device scratch (allocation-free)
// ---------------------------------------------------------------------------
__device__ float g_Wt[DIN * NB * DOUT];            // [(i*9+k)][o], 576 KB
__device__ float g_beta[DOUT];
__device__ float g_part[KSPLIT * BATCH * DOUT];    // 8 MB fp32 partials
__device__ int   g_cnt[NTILE];                     // split-arrival counters

typedef unsigned long long ull;

// ---------------------------------------------------------------------------
// Helpers
// ---------------------------------------------------------------------------
__device__ __forceinline__ void ffma2(ull& d, ull a, ull b) {
    // packed dual fp32 FMA (Blackwell); ptxas never emits this from C++
    asm("fma.rn.f32x2 %0, %1, %2, %0;" : "+l"(d) : "l"(a), "l"(b));
}
__device__ __forceinline__ float lo32(ull v) { return __uint_as_float((unsigned)v); }
__device__ __forceinline__ float hi32(ull v) { return __uint_as_float((unsigned)(v >> 32)); }
__device__ __forceinline__ float tanh_ap(float f) {
    float r; asm("tanh.approx.f32 %0, %1;" : "=f"(r) : "f"(f)); return r;
}
__device__ __forceinline__ float sqrt_ap(float f) {
    float r; asm("sqrt.approx.f32 %0, %1;" : "=f"(r) : "f"(f)); return r;
}

// ---------------------------------------------------------------------------
// Prep: Wt[(i,k),o] = W[i,o,k] * C[i,o]   (same as round-1, validated)
// ---------------------------------------------------------------------------
__global__ void kan_prep(const float* __restrict__ W, const float* __restrict__ C) {
    int idx = blockIdx.x * blockDim.x + threadIdx.x;   // over Din*Dout*NB
    if (idx < DIN * DOUT * NB) {
        int k = idx % NB;
        int o = (idx / NB) % DOUT;
        int i = idx / (NB * DOUT);
        g_Wt[(i * NB + k) * DOUT + o] = W[idx] * C[i * DOUT + o];
    }
}

// beta[o] = sum_i bias[i,o] * C[i,o]; also re-zero split counters (graph-safe)
__global__ void kan_beta(const float* __restrict__ bias, const float* __restrict__ C) {
    int o = threadIdx.x;
    float s = 0.0f;
    #pragma unroll 8
    for (int i = 0; i < DIN; ++i)
        s += bias[i * DOUT + o] * C[i * DOUT + o];
    g_beta[o] = s;
    if (o < NTILE) g_cnt[o] = 0;
}

// ---------------------------------------------------------------------------
// Main: fused basis + FFMA2 GEMM, split-K over Din, fused final reduction.
// Grid (32, 4), 256 threads. 128x128 tile, 8x8 micro-tile per thread.
// ---------------------------------------------------------------------------
__global__ __launch_bounds__(256, 1)
void kan_main(const float* __restrict__ x, float* __restrict__ out) {
    __shared__ float Xs[BM * 33];           // staged x tile, padded stride
    __shared__ float Asd[2 * NB * 256];     // feats, each value DUPLICATED {v,v}
    __shared__ float Bs[2 * NB * DOUT];     // Wt rows for 2 input dims
    __shared__ int   s_last;

    const int tid   = threadIdx.x;
    const int bm0   = blockIdx.x * BM;
    const int split = blockIdx.y;
    const int i0    = split * ISPLIT;
    const int row   = tid & 127;            // feat-producer row
    const int isub  = tid >> 7;             // which of the 2 input dims
    const int col0  = (tid & 15) * 8;       // consumer micro-tile origin
    const int row0  = (tid >> 4) * 8;

    // --- stage X tile [128 rows][32 i] (coalesced float4, padded stride 33)
    for (int j = tid; j < BM * 8; j += 256) {
        int r = j >> 3, q = j & 7;
        float4 v = *(const float4*)(x + (size_t)(bm0 + r) * DIN + i0 + q * 4);
        float* d = Xs + r * 33 + q * 4;
        d[0] = v.x; d[1] = v.y; d[2] = v.z; d[3] = v.w;
    }

    ull acc[8][4];
    #pragma unroll
    for (int r = 0; r < 8; ++r)
        #pragma unroll
        for (int c = 0; c < 4; ++c) acc[r][c] = 0ull;

    // --- prefetch B for iteration 0 (2 dims x 9 x 128 = 576 float4)
    float4 breg[3];
    {
        const float4* src = (const float4*)g_Wt + (size_t)i0 * 288;
        #pragma unroll
        for (int jj = 0; jj < 3; ++jj) {
            int j = tid + jj * 256;
            if (j < 576) breg[jj] = src[j];
        }
    }

    #pragma unroll 1
    for (int c = 0; c < NITER; ++c) {
        __syncthreads();   // previous iteration's FMA done before smem overwrite

        // --- feats for (row, i_local = 2c + isub), stored duplicated {v,v}
        {
            float xv = Xs[row * 33 + 2 * c + isub];
            float ax = fabsf(xv);
            float x2 = xv * xv;
            float2* d = (float2*)(Asd + isub * NB * 256) + row;  // stride 128 float2 per k
            d[0 * 128] = make_float2(xv, xv);
            d[1 * 128] = make_float2(x2, x2);
            float x3 = x2 * xv;            d[2 * 128] = make_float2(x3, x3);
            float e  = __expf(xv);         d[3 * 128] = make_float2(e, e);
            float lg = __logf(ax + 1.0f);  d[4 * 128] = make_float2(lg, lg);
            float sq = sqrt_ap(ax);        d[5 * 128] = make_float2(sq, sq);
            float th = tanh_ap(xv);        d[6 * 128] = make_float2(th, th);
            float sn = __sinf(xv);         d[7 * 128] = make_float2(sn, sn);
            d[8 * 128] = make_float2(ax, ax);
        }
        // --- store B tile from prefetch registers
        {
            float4* bd = (float4*)Bs;
            #pragma unroll
            for (int jj = 0; jj < 3; ++jj) {
                int j = tid + jj * 256;
                if (j < 576) bd[j] = breg[jj];
            }
        }
        // --- prefetch next iteration's B
        if (c + 1 < NITER) {
            const float4* src = (const float4*)g_Wt + (size_t)(i0 + 2 * (c + 1)) * 288;
            #pragma unroll
            for (int jj = 0; jj < 3; ++jj) {
                int j = tid + jj * 256;
                if (j < 576) breg[jj] = src[j];
            }
        }
        __syncthreads();

        // --- 8x8 micro-tile FMA via packed f32x2, 18 k-steps
        #pragma unroll
        for (int s2 = 0; s2 < 2; ++s2) {
            #pragma unroll
            for (int k = 0; k < NB; ++k) {
                const float* ab = Asd + (s2 * NB + k) * 256 + 2 * row0;
                ulonglong2 a01 = *(const ulonglong2*)(ab);
                ulonglong2 a23 = *(const ulonglong2*)(ab + 4);
                ulonglong2 a45 = *(const ulonglong2*)(ab + 8);
                ulonglong2 a67 = *(const ulonglong2*)(ab + 12);
                const float* bp = Bs + (s2 * NB + k) * DOUT + col0;
                ulonglong2 b01 = *(const ulonglong2*)(bp);
                ulonglong2 b23 = *(const ulonglong2*)(bp + 4);
                ull aa[8] = {a01.x, a01.y, a23.x, a23.y, a45.x, a45.y, a67.x, a67.y};
                ull bv[4] = {b01.x, b01.y, b23.x, b23.y};
                #pragma unroll
                for (int r = 0; r < 8; ++r)
                    #pragma unroll
                    for (int cc = 0; cc < 4; ++cc)
                        ffma2(acc[r][cc], aa[r], bv[cc]);
            }
        }
    }

    // --- write fp32 partials (coalesced float4)
    {
        float* outp = g_part + ((size_t)split * BATCH + bm0 + row0) * DOUT + col0;
        #pragma unroll
        for (int r = 0; r < 8; ++r) {
            float4 v0 = make_float4(lo32(acc[r][0]), hi32(acc[r][0]),
                                    lo32(acc[r][1]), hi32(acc[r][1]));
            float4 v1 = make_float4(lo32(acc[r][2]), hi32(acc[r][2]),
                                    lo32(acc[r][3]), hi32(acc[r][3]));
            *(float4*)(outp + (size_t)r * DOUT)     = v0;
            *(float4*)(outp + (size_t)r * DOUT + 4) = v1;
        }
    }

    // --- last split block of this batch tile performs the final reduction
    __threadfence();
    __syncthreads();
    if (tid == 0)
        s_last = (atomicAdd(&g_cnt[blockIdx.x], 1) == KSPLIT - 1);
    __syncthreads();

    if (s_last) {
        __threadfence();
        const float4* pp  = (const float4*)g_part;
        const float4* bb4 = (const float4*)g_beta;
        const size_t plane = (size_t)BATCH * DOUT / 4;
        const size_t t4    = (size_t)bm0 * (DOUT / 4);
        for (int idx = tid; idx < BM * DOUT / 4; idx += 256) {
            float4 s = bb4[idx & 31];
            size_t o = t4 + idx;
            #pragma unroll
            for (int sp = 0; sp < KSPLIT; ++sp) {
                float4 p = __ldcg(pp + sp * plane + o);
                s.x += p.x; s.y += p.y; s.z += p.z; s.w += p.w;
            }
            ((float4*)out)[o] = s;
        }
    }
}

// ---------------------------------------------------------------------------
extern "C" void kernel_launch(void* const* d_in, const int* in_sizes, int n_in,
                              void* d_out, int out_size) {
    const float* x    = (const float*)d_in[0];   // [4096,128]
    const float* W    = (const float*)d_in[1];   // [128,128,9]
    const float* bias = (const float*)d_in[2];   // [128,128]
    const float* C    = (const float*)d_in[3];   // [128,128]
    float* out        = (float*)d_out;           // [4096,128]
    (void)in_sizes; (void)n_in; (void)out_size;

    kan_prep<<<(DIN * DOUT * NB + 255) / 256, 256>>>(W, C);
    kan_beta<<<1, DOUT>>>(bias, C);
    kan_main<<<dim3(NTILE, KSPLIT), 256>>>(x, out);
}

// round 4
// speedup vs baseline: 1.9766x; 1.7091x over previous
#include <cuda_runtime.h>
#include <cstdint>
#include <math.h>

// ---------------------------------------------------------------------------
// Problem constants
// ---------------------------------------------------------------------------
#define BATCH   4096
#define DIN     128
#define DOUT    128
#define NB      9
#define KTOT    (DIN * NB)         // 1152, i-major: k = i*9 + kb
#define KSPLIT  4
#define KSLICE  (KTOT / KSPLIT)    // 288 k per split (32 input dims)
#define CHUNK   72                 // k per smem chunk (8 input dims, 9 k8-steps)
#define NCHUNK  (KSLICE / CHUNK)   // 4
#define BM      128
#define NTILE   (BATCH / BM)       // 32

// smem strides (floats) — both conflict-free for the mma load patterns
#define ASTR    77
#define BSTR    76
// smem layout (floats): Xs[128*33] | As[128*77] | Bs[128*76]
#define XS_F    (BM * 33)
#define AS_F    (BM * ASTR)
#define BS_F    (DOUT * BSTR)
#define SMEM_BYTES ((XS_F + AS_F + BS_F) * 4)

// ---------------------------------------------------------------------------
// Device scratch (allocation-free)
// ---------------------------------------------------------------------------
__device__ float g_Wt[DOUT * KTOT];                // B[o][k], tf32-rounded, 576 KB
__device__ float g_beta[DOUT];
__device__ float g_part[KSPLIT * BATCH * DOUT];    // 8 MB fp32 partials
__device__ int   g_cnt[NTILE];

// ---------------------------------------------------------------------------
// Helpers
// ---------------------------------------------------------------------------
__device__ __forceinline__ float tf32r(float f) {
    float r; asm("cvt.rna.tf32.f32 %0, %1;" : "=f"(r) : "f"(f)); return r;
}
__device__ __forceinline__ float tanh_ap(float f) {
    float r; asm("tanh.approx.f32 %0, %1;" : "=f"(r) : "f"(f)); return r;
}
__device__ __forceinline__ float sqrt_ap(float f) {
    float r; asm("sqrt.approx.f32 %0, %1;" : "=f"(r) : "f"(f)); return r;
}
__device__ __forceinline__ uint32_t fbits(float f) { return __float_as_uint(f); }

// m16n8k8 tf32 mma: D += A*B, fp32 accumulate
__device__ __forceinline__ void mma_tf32(float* d, const uint32_t* a, const uint32_t* b) {
    asm volatile(
        "mma.sync.aligned.m16n8k8.row.col.f32.tf32.tf32.f32 "
        "{%0,%1,%2,%3}, {%4,%5,%6,%7}, {%8,%9}, {%0,%1,%2,%3};"
        : "+f"(d[0]), "+f"(d[1]), "+f"(d[2]), "+f"(d[3])
        : "r"(a[0]), "r"(a[1]), "r"(a[2]), "r"(a[3]), "r"(b[0]), "r"(b[1]));
}

// ---------------------------------------------------------------------------
// Prep: g_Wt[o][i*9+kb] = tf32(W[i,o,kb] * C[i,o]) — writes fully coalesced
// ---------------------------------------------------------------------------
__global__ void kan_prep(const float* __restrict__ W, const float* __restrict__ C) {
    int j = blockIdx.x * blockDim.x + threadIdx.x;    // linear over g_Wt
    if (j < DOUT * KTOT) {
        int kk = j % KTOT;          // i*9 + kb
        int o  = j / KTOT;
        int i  = kk / NB;
        int kb = kk - i * NB;
        g_Wt[j] = tf32r(W[(i * DOUT + o) * NB + kb] * C[i * DOUT + o]);
    }
}

// beta[o] = sum_i bias[i,o] * C[i,o]; re-zero split counters (graph-safe)
__global__ void kan_beta(const float* __restrict__ bias, const float* __restrict__ C) {
    int o = threadIdx.x;
    float s = 0.0f;
    #pragma unroll 8
    for (int i = 0; i < DIN; ++i)
        s += bias[i * DOUT + o] * C[i * DOUT + o];
    g_beta[o] = s;
    if (o < NTILE) g_cnt[o] = 0;
}

// ---------------------------------------------------------------------------
// Main: fused basis + tf32 mma.sync GEMM, split-K, fused last-block reduce.
// Grid (32, 4), 256 threads (8 warps; warp tile 32 m x 64 n).
// ---------------------------------------------------------------------------
__global__ __launch_bounds__(256, 1)
void kan_main(const float* __restrict__ x, float* __restrict__ out) {
    extern __shared__ float smem[];
    float* Xs = smem;              // [128][33]
    float* As = smem + XS_F;       // [128 rows][77], cols 0..71 used
    float* Bs = As + AS_F;         // [128 n][76],   cols 0..71 used
    __shared__ int s_last;

    const int tid   = threadIdx.x;
    const int lane  = tid & 31;
    const int warp  = tid >> 5;
    const int wm    = warp & 3;          // m warp: 0..3  -> m0 = wm*32
    const int wn    = warp >> 2;         // n warp: 0..1  -> n0 = wn*64
    const int g     = lane >> 2;         // groupID (0..7)
    const int tg    = lane & 3;          // thread-in-group
    const int bm0   = blockIdx.x * BM;
    const int split = blockIdx.y;
    const int i0    = split * (DIN / KSPLIT);   // first input dim of slice
    const int koff0 = split * KSLICE;           // first k of slice

    // --- stage X tile [128 rows][32 i] (coalesced float4, padded stride 33)
    for (int j = tid; j < BM * 8; j += 256) {
        int r = j >> 3, q = j & 7;
        float4 v = *(const float4*)(x + (size_t)(bm0 + r) * DIN + i0 + q * 4);
        float* d = Xs + r * 33 + q * 4;
        d[0] = v.x; d[1] = v.y; d[2] = v.z; d[3] = v.w;
    }

    float acc[2][8][4];
    #pragma unroll
    for (int mt = 0; mt < 2; ++mt)
        #pragma unroll
        for (int nt = 0; nt < 8; ++nt)
            #pragma unroll
            for (int e = 0; e < 4; ++e) acc[mt][nt][e] = 0.0f;

    for (int c = 0; c < NCHUNK; ++c) {
        __syncthreads();   // previous chunk's mma reads done

        // --- produce feats: 128 rows x 8 input dims -> As[row][ii*9+kb] (tf32)
        #pragma unroll
        for (int jj = 0; jj < 4; ++jj) {
            int j   = tid + jj * 256;     // < 1024
            int row = j & 127;
            int ii  = j >> 7;             // 0..7
            float xv = Xs[row * 33 + c * 8 + ii];
            float ax = fabsf(xv);
            float x2 = xv * xv;
            float* d = As + row * ASTR + ii * NB;
            d[0] = tf32r(xv);
            d[1] = tf32r(x2);
            d[2] = tf32r(x2 * xv);
            d[3] = tf32r(__expf(xv));
            d[4] = tf32r(__logf(ax + 1.0f));
            d[5] = tf32r(sqrt_ap(ax));
            d[6] = tf32r(tanh_ap(xv));
            d[7] = tf32r(__sinf(xv));
            d[8] = tf32r(ax);
        }
        // --- stage B chunk: g_Wt[n][koff .. koff+71] -> Bs[n][0..71]
        {
            const int koff = koff0 + c * CHUNK;
            #pragma unroll
            for (int jj = 0; jj < 9; ++jj) {
                int j = tid + jj * 256;   // < 2304 (128 n x 18 float4)
                int n = j / 18, q = j - n * 18;
                float4 v = *(const float4*)(g_Wt + (size_t)n * KTOT + koff + q * 4);
                *(float4*)(Bs + n * BSTR + q * 4) = v;
            }
        }
        __syncthreads();

        // --- 9 k8-steps of m16n8k8 tf32 mma
        #pragma unroll
        for (int ks = 0; ks < CHUNK / 8; ++ks) {
            const int kb = ks * 8 + tg;
            uint32_t a[2][4];
            #pragma unroll
            for (int mt = 0; mt < 2; ++mt) {
                const float* ap = As + (wm * 32 + mt * 16 + g) * ASTR + kb;
                a[mt][0] = fbits(ap[0]);
                a[mt][1] = fbits(ap[8 * ASTR]);
                a[mt][2] = fbits(ap[4]);
                a[mt][3] = fbits(ap[8 * ASTR + 4]);
            }
            uint32_t b[8][2];
            #pragma unroll
            for (int nt = 0; nt < 8; ++nt) {
                const float* bp = Bs + (wn * 64 + nt * 8 + g) * BSTR + kb;
                b[nt][0] = fbits(bp[0]);
                b[nt][1] = fbits(bp[4]);
            }
            #pragma unroll
            for (int mt = 0; mt < 2; ++mt)
                #pragma unroll
                for (int nt = 0; nt < 8; ++nt)
                    mma_tf32(acc[mt][nt], a[mt], b[nt]);
        }
    }

    // --- write fp32 partials (float2 per fragment row)
    {
        float* base = g_part + (size_t)split * BATCH * DOUT;
        #pragma unroll
        for (int mt = 0; mt < 2; ++mt) {
            #pragma unroll
            for (int nt = 0; nt < 8; ++nt) {
                int row = bm0 + wm * 32 + mt * 16 + g;
                int col = wn * 64 + nt * 8 + tg * 2;
                float* p = base + (size_t)row * DOUT + col;
                *(float2*)p                      = make_float2(acc[mt][nt][0], acc[mt][nt][1]);
                *(float2*)(p + 8 * DOUT)         = make_float2(acc[mt][nt][2], acc[mt][nt][3]);
            }
        }
    }

    // --- last split block of this batch tile does the final reduction
    __threadfence();
    __syncthreads();
    if (tid == 0)
        s_last = (atomicAdd(&g_cnt[blockIdx.x], 1) == KSPLIT - 1);
    __syncthreads();

    if (s_last) {
        __threadfence();
        const float4* pp  = (const float4*)g_part;
        const float4* bb4 = (const float4*)g_beta;
        const size_t plane = (size_t)BATCH * DOUT / 4;
        const size_t t4    = (size_t)bm0 * (DOUT / 4);
        for (int idx = tid; idx < BM * DOUT / 4; idx += 256) {
            float4 s = bb4[idx & 31];
            size_t o = t4 + idx;
            #pragma unroll
            for (int sp = 0; sp < KSPLIT; ++sp) {
                float4 p = __ldcg(pp + sp * plane + o);
                s.x += p.x; s.y += p.y; s.z += p.z; s.w += p.w;
            }
            ((float4*)out)[o] = s;
        }
    }
}

// ---------------------------------------------------------------------------
extern "C" void kernel_launch(void* const* d_in, const int* in_sizes, int n_in,
                              void* d_out, int out_size) {
    const float* x    = (const float*)d_in[0];   // [4096,128]
    const float* W    = (const float*)d_in[1];   // [128,128,9]
    const float* bias = (const float*)d_in[2];   // [128,128]
    const float* C    = (const float*)d_in[3];   // [128,128]
    float* out        = (float*)d_out;           // [4096,128]
    (void)in_sizes; (void)n_in; (void)out_size;

    cudaFuncSetAttribute(kan_main, cudaFuncAttributeMaxDynamicSharedMemorySize, SMEM_BYTES);

    kan_prep<<<(DOUT * KTOT + 255) / 256, 256>>>(W, C);
    kan_beta<<<1, DOUT>>>(bias, C);
    kan_main<<<dim3(NTILE, KSPLIT), 256, SMEM_BYTES>>>(x, out);
}

// round 5
// speedup vs baseline: 2.0915x; 1.0581x over previous
#include <cuda_runtime.h>
#include <cstdint>
#include <math.h>

// ---------------------------------------------------------------------------
// Problem constants
// ---------------------------------------------------------------------------
#define BATCH   4096
#define DIN     128
#define DOUT    128
#define NB      9
#define KTOT    (DIN * NB)         // 1152, i-major: k = i*9 + kb
#define KSPLIT  4
#define KSLICE  (KTOT / KSPLIT)    // 288 k per split (32 input dims)
#define CHUNK   72                 // 8 input dims, 9 k8-steps
#define NCHUNK  (KSLICE / CHUNK)   // 4
#define BM      64
#define NTILE   (BATCH / BM)       // 64

#define ASTR    76
#define BSTR    76
#define XS_F    (BM * 33)          // 2112
#define AS_F    (BM * ASTR)        // 4864
#define BS_F    (DOUT * BSTR)      // 9728 per stage
#define SMEM_BYTES ((XS_F + AS_F + 2 * BS_F) * 4)   // 105,728 B

// ---------------------------------------------------------------------------
// Device scratch (allocation-free)
// ---------------------------------------------------------------------------
__device__ float g_Wt[DOUT * KTOT];                // B[o][k] tf32, 576 KB
__device__ float g_beta[DOUT];
__device__ float g_part[KSPLIT * BATCH * DOUT];    // 8 MB fp32 partials
__device__ int   g_cnt[NTILE];

// ---------------------------------------------------------------------------
// Helpers
// ---------------------------------------------------------------------------
__device__ __forceinline__ float tf32r(float f) {
    float r; asm("cvt.rna.tf32.f32 %0, %1;" : "=f"(r) : "f"(f)); return r;
}
__device__ __forceinline__ float tanh_ap(float f) {
    float r; asm("tanh.approx.f32 %0, %1;" : "=f"(r) : "f"(f)); return r;
}
__device__ __forceinline__ float sqrt_ap(float f) {
    float r; asm("sqrt.approx.f32 %0, %1;" : "=f"(r) : "f"(f)); return r;
}
__device__ __forceinline__ uint32_t fbits(float f) { return __float_as_uint(f); }
__device__ __forceinline__ uint32_t s2u(const void* p) {
    uint32_t a;
    asm("{ .reg .u64 t; cvta.to.shared.u64 t, %1; cvt.u32.u64 %0, t; }" : "=r"(a) : "l"(p));
    return a;
}
__device__ __forceinline__ void cp16(uint32_t dst, const void* src) {
    asm volatile("cp.async.cg.shared.global [%0], [%1], 16;" :: "r"(dst), "l"(src) : "memory");
}
#define CP_COMMIT() asm volatile("cp.async.commit_group;" ::: "memory")
#define CP_WAIT1()  asm volatile("cp.async.wait_group 1;"  ::: "memory")
#define CP_WAIT0()  asm volatile("cp.async.wait_group 0;"  ::: "memory")

// m16n8k8 tf32 mma: D += A*B, fp32 accumulate
__device__ __forceinline__ void mma_tf32(float* d, const uint32_t* a, const uint32_t* b) {
    asm volatile(
        "mma.sync.aligned.m16n8k8.row.col.f32.tf32.tf32.f32 "
        "{%0,%1,%2,%3}, {%4,%5,%6,%7}, {%8,%9}, {%0,%1,%2,%3};"
        : "+f"(d[0]), "+f"(d[1]), "+f"(d[2]), "+f"(d[3])
        : "r"(a[0]), "r"(a[1]), "r"(a[2]), "r"(a[3]), "r"(b[0]), "r"(b[1]));
}

// ---------------------------------------------------------------------------
// Prep: one block per input dim i; thread o handles W[i,o,:] (contiguous) and
// writes g_Wt[o][i*9 .. i*9+8] (contiguous per thread). ~1 us.
// ---------------------------------------------------------------------------
__global__ void kan_prep(const float* __restrict__ W, const float* __restrict__ C) {
    const int i = blockIdx.x;
    const int o = threadIdx.x;
    float cv = C[i * DOUT + o];
    const float* wp = W + ((size_t)i * DOUT + o) * NB;
    float* dp = g_Wt + (size_t)o * KTOT + i * NB;
    #pragma unroll
    for (int kb = 0; kb < NB; ++kb)
        dp[kb] = tf32r(wp[kb] * cv);
}

// beta[o] = sum_i bias[i,o]*C[i,o] (2 threads per o), zero split counters
__global__ void kan_beta(const float* __restrict__ bias, const float* __restrict__ C) {
    const int t = threadIdx.x;
    const int o = t >> 1;
    const int h = t & 1;
    float s = 0.0f;
    #pragma unroll 8
    for (int i = h * 64; i < h * 64 + 64; ++i)
        s += bias[i * DOUT + o] * C[i * DOUT + o];
    s += __shfl_xor_sync(0xffffffffu, s, 1);
    if (h == 0) g_beta[o] = s;
    if (t < NTILE) g_cnt[t] = 0;
}

// ---------------------------------------------------------------------------
// Main: fused basis + tf32 mma, cp.async double-buffered B, 2 CTAs/SM,
// split-K over Din with fused last-block reduction.
// Grid (64, 4), 256 threads (8 warps; warp tile 32m x 32n).
// ---------------------------------------------------------------------------
__global__ __launch_bounds__(256, 2)
void kan_main(const float* __restrict__ x, float* __restrict__ out) {
    extern __shared__ float smem[];
    float* Xs  = smem;                  // [64][33]
    float* As  = smem + XS_F;           // [64][76], cols 0..71 used
    float* Bs0 = As + AS_F;             // two stages of [128][76]
    __shared__ int s_last;

    const int tid   = threadIdx.x;
    const int lane  = tid & 31;
    const int warp  = tid >> 5;
    const int wm    = warp & 1;          // m warp -> m0 = wm*32
    const int wn    = warp >> 1;         // n warp -> n0 = wn*32
    const int g     = lane >> 2;
    const int tg    = lane & 3;
    const int bm0   = blockIdx.x * BM;
    const int split = blockIdx.y;
    const int i0    = split * (DIN / KSPLIT);
    const int koff0 = split * KSLICE;

    // --- stage X tile [64 rows][32 i] (coalesced float4, padded stride 33)
    #pragma unroll
    for (int jj = 0; jj < 2; ++jj) {
        int j = tid + jj * 256;
        int r = j >> 3, q = j & 7;
        float4 v = *(const float4*)(x + (size_t)(bm0 + r) * DIN + i0 + q * 4);
        float* d = Xs + r * 33 + q * 4;
        d[0] = v.x; d[1] = v.y; d[2] = v.z; d[3] = v.w;
    }

    // --- cp.async B chunk 0 into stage 0
    const uint32_t bs_u32[2] = { s2u(Bs0), s2u(Bs0 + BS_F) };
    {
        #pragma unroll
        for (int jj = 0; jj < 9; ++jj) {
            int j = tid + jj * 256;           // 2304 float4
            int n = j / 18, q = j - n * 18;
            cp16(bs_u32[0] + (uint32_t)(n * BSTR + q * 4) * 4,
                 g_Wt + (size_t)n * KTOT + koff0 + q * 4);
        }
        CP_COMMIT();
    }

    float acc[2][4][4];
    #pragma unroll
    for (int mt = 0; mt < 2; ++mt)
        #pragma unroll
        for (int nt = 0; nt < 4; ++nt)
            #pragma unroll
            for (int e = 0; e < 4; ++e) acc[mt][nt][e] = 0.0f;

    for (int c = 0; c < NCHUNK; ++c) {
        __syncthreads();   // prior chunk's mma reads of As / Bs[(c+1)&1] done

        // --- feats: 64 rows x 8 dims, 2 per thread -> As[row][ii*9+kb] (tf32)
        #pragma unroll
        for (int jj = 0; jj < 2; ++jj) {
            int j   = tid + jj * 256;
            int row = j & 63;
            int ii  = j >> 6;
            float xv = Xs[row * 33 + c * 8 + ii];
            float ax = fabsf(xv);
            float x2 = xv * xv;
            float* d = As + row * ASTR + ii * NB;
            d[0] = tf32r(xv);
            d[1] = tf32r(x2);
            d[2] = tf32r(x2 * xv);
            d[3] = tf32r(__expf(xv));
            d[4] = tf32r(__logf(ax + 1.0f));
            d[5] = tf32r(sqrt_ap(ax));
            d[6] = tf32r(tanh_ap(xv));
            d[7] = tf32r(__sinf(xv));
            d[8] = tf32r(ax);
        }

        // --- cp.async next B chunk into the other stage (overlaps this mma)
        if (c + 1 < NCHUNK) {
            const int koff = koff0 + (c + 1) * CHUNK;
            const uint32_t dst = bs_u32[(c + 1) & 1];
            #pragma unroll
            for (int jj = 0; jj < 9; ++jj) {
                int j = tid + jj * 256;
                int n = j / 18, q = j - n * 18;
                cp16(dst + (uint32_t)(n * BSTR + q * 4) * 4,
                     g_Wt + (size_t)n * KTOT + koff + q * 4);
            }
            CP_COMMIT();
            CP_WAIT1();       // chunk c's group complete
        } else {
            CP_WAIT0();
        }
        __syncthreads();

        // --- 9 k8-steps of m16n8k8 tf32 mma on stage c&1
        const float* Bsc = Bs0 + (c & 1) * BS_F;
        #pragma unroll
        for (int ks = 0; ks < CHUNK / 8; ++ks) {
            const int kb = ks * 8 + tg;
            uint32_t a[2][4];
            #pragma unroll
            for (int mt = 0; mt < 2; ++mt) {
                const float* ap = As + (wm * 32 + mt * 16 + g) * ASTR + kb;
                a[mt][0] = fbits(ap[0]);
                a[mt][1] = fbits(ap[8 * ASTR]);
                a[mt][2] = fbits(ap[4]);
                a[mt][3] = fbits(ap[8 * ASTR + 4]);
            }
            uint32_t b[4][2];
            #pragma unroll
            for (int nt = 0; nt < 4; ++nt) {
                const float* bp = Bsc + (wn * 32 + nt * 8 + g) * BSTR + kb;
                b[nt][0] = fbits(bp[0]);
                b[nt][1] = fbits(bp[4]);
            }
            #pragma unroll
            for (int mt = 0; mt < 2; ++mt)
                #pragma unroll
                for (int nt = 0; nt < 4; ++nt)
                    mma_tf32(acc[mt][nt], a[mt], b[nt]);
        }
    }

    // --- write fp32 partials
    {
        float* base = g_part + (size_t)split * BATCH * DOUT;
        #pragma unroll
        for (int mt = 0; mt < 2; ++mt) {
            #pragma unroll
            for (int nt = 0; nt < 4; ++nt) {
                int row = bm0 + wm * 32 + mt * 16 + g;
                int col = wn * 32 + nt * 8 + tg * 2;
                float* p = base + (size_t)row * DOUT + col;
                *(float2*)p              = make_float2(acc[mt][nt][0], acc[mt][nt][1]);
                *(float2*)(p + 8 * DOUT) = make_float2(acc[mt][nt][2], acc[mt][nt][3]);
            }
        }
    }

    // --- last split block of this batch tile does the final reduction
    __threadfence();
    __syncthreads();
    if (tid == 0)
        s_last = (atomicAdd(&g_cnt[blockIdx.x], 1) == KSPLIT - 1);
    __syncthreads();

    if (s_last) {
        __threadfence();
        const float4* pp  = (const float4*)g_part;
        const float4* bb4 = (const float4*)g_beta;
        const size_t plane = (size_t)BATCH * DOUT / 4;
        const size_t t4    = (size_t)bm0 * (DOUT / 4);
        #pragma unroll
        for (int idx = tid; idx < BM * DOUT / 4; idx += 256) {
            float4 s = bb4[idx & 31];
            size_t o = t4 + idx;
            #pragma unroll
            for (int sp = 0; sp < KSPLIT; ++sp) {
                float4 p = __ldcg(pp + sp * plane + o);
                s.x += p.x; s.y += p.y; s.z += p.z; s.w += p.w;
            }
            ((float4*)out)[o] = s;
        }
    }
}

// ---------------------------------------------------------------------------
extern "C" void kernel_launch(void* const* d_in, const int* in_sizes, int n_in,
                              void* d_out, int out_size) {
    const float* x    = (const float*)d_in[0];   // [4096,128]
    const float* W    = (const float*)d_in[1];   // [128,128,9]
    const float* bias = (const float*)d_in[2];   // [128,128]
    const float* C    = (const float*)d_in[3];   // [128,128]
    float* out        = (float*)d_out;           // [4096,128]
    (void)in_sizes; (void)n_in; (void)out_size;

    cudaFuncSetAttribute(kan_main, cudaFuncAttributeMaxDynamicSharedMemorySize, SMEM_BYTES);

    kan_prep<<<DIN, DOUT>>>(W, C);
    kan_beta<<<1, 256>>>(bias, C);
    kan_main<<<dim3(NTILE, KSPLIT), 256, SMEM_BYTES>>>(x, out);
}